// round 6
// baseline (speedup 1.0000x reference)
#include <cuda_runtime.h>
#include <math.h>

// Problem constants (from reference setup_inputs)
#define BATCH   4096
#define HID     1024
#define EMBD    64
#define NOBS    8            // SEQ-1 observed steps
#define NSTEPS  19           // 8 + (n_predict-1) = 8 + 11

// GEMM tiling
#define TM      64           // batch rows per block
#define TN      32           // cols per gate per block (x4 gates => 128 W rows)
#define TN4     128
#define TK      32
#define NCHUNK  34           // 2 chunks of emb (K=64) + 32 chunks of h (K=1024)

#define AS_STRIDE  68        // padded strides (floats)
#define WS_STRIDE  132
#define GB_MSTRIDE 33
#define GB_GSTRIDE (64*33)

// Scratch state (allocation-free): double-buffered h + cell state c
__device__ float g_h[2][BATCH * HID];
__device__ float g_c[BATCH * HID];

__device__ __forceinline__ float sigf(float x) { return 1.0f / (1.0f + __expf(-x)); }

// One LSTM step: emb -> gates GEMM -> cell update. Writes h (double buffer) and c.
extern "C" __global__ void __launch_bounds__(256)
lstm_step_kernel(const float* __restrict__ observed,
                 const float* __restrict__ W_emb, const float* __restrict__ b_emb,
                 const float* __restrict__ W_ih,  const float* __restrict__ b_ih,
                 const float* __restrict__ W_hh,  const float* __restrict__ b_hh,
                 const float* __restrict__ out,   int s)
{
    extern __shared__ float sm[];
    float* emb_s = sm;                           // [EMBD][AS_STRIDE]  (k-major: [e][m])
    float* A_s   = sm + EMBD * AS_STRIDE;        // [TK][AS_STRIDE]
    float* W_s   = A_s + TK * AS_STRIDE;         // [TK][WS_STRIDE]
    float* gbuf  = sm;                           // overlay after GEMM: [4][64][GB_MSTRIDE]

    const int tid = threadIdx.x;
    const int bn  = blockIdx.x;   // 0..31  (H tile)
    const int bm  = blockIdx.y;   // 0..63  (B tile)

    const float* h_in  = g_h[(s & 1) ^ 1];
    float*       h_out = g_h[s & 1];

    // ---- embedding tile: emb_s[e][m] = relu(W_emb[e,:] . d[m] + b_emb[e]) ----
    #pragma unroll
    for (int u = 0; u < 16; ++u) {
        int idx = tid + 256 * u;          // 0..4095
        int m = idx >> 6, e = idx & 63;
        int row = bm * TM + m;
        float d0, d1;
        if (s < NOBS) {
            const float* o1 = observed + (size_t)(s + 1) * BATCH * 2 + (size_t)row * 2;
            const float* o0 = observed + (size_t)s       * BATCH * 2 + (size_t)row * 2;
            d0 = o1[0] - o0[0];
            d1 = o1[1] - o0[1];
        } else {
            const float* pv = out + (size_t)(s - 1) * BATCH * 5 + (size_t)row * 5;
            d0 = pv[0];
            d1 = pv[1];
        }
        float v = fmaf(W_emb[e * 2], d0, fmaf(W_emb[e * 2 + 1], d1, b_emb[e]));
        emb_s[e * AS_STRIDE + m] = fmaxf(v, 0.0f);
    }

    // ---- accumulators init = b_ih + b_hh ----
    const int tx = tid & 15;   // -> 8 n's: n = tx*8..tx*8+7 (within 128 combined gate cols)
    const int ty = tid >> 4;   // -> 4 m's: m = ty*4..ty*4+3
    float acc[4][8];
    #pragma unroll
    for (int ni = 0; ni < 8; ++ni) {
        int n = tx * 8 + ni;
        int r = (n >> 5) * HID + bn * TN + (n & 31);
        float bv = b_ih[r] + b_hh[r];
        #pragma unroll
        for (int mi = 0; mi < 4; ++mi) acc[mi][ni] = bv;
    }

    const int lr = tid >> 3;   // 0..31 (row within a load pass)
    const int kq = tid & 7;    // 0..7  (float4 slot along K)

    const int nchunk = (s == 0) ? 2 : NCHUNK;   // step 0: h==0, only emb K-chunks
    __syncthreads();  // emb_s ready

    for (int kc = 0; kc < nchunk; ++kc) {
        const float* Wsrc;
        int kb, ldw;
        if (kc < 2) { Wsrc = W_ih; kb = kc * TK;        ldw = EMBD; }
        else        { Wsrc = W_hh; kb = kc * TK - EMBD; ldw = HID;  }

        // load W tile [TN4 x TK] transposed into W_s[k][n]
        #pragma unroll
        for (int p = 0; p < 4; ++p) {
            int n = p * 32 + lr;
            int r = (n >> 5) * HID + bn * TN + (n & 31);
            float4 w = *(const float4*)(Wsrc + (size_t)r * ldw + kb + kq * 4);
            W_s[(kq * 4 + 0) * WS_STRIDE + n] = w.x;
            W_s[(kq * 4 + 1) * WS_STRIDE + n] = w.y;
            W_s[(kq * 4 + 2) * WS_STRIDE + n] = w.z;
            W_s[(kq * 4 + 3) * WS_STRIDE + n] = w.w;
        }
        // load A (h) tile [TM x TK] transposed into A_s[k][m] (only for h chunks)
        if (kc >= 2) {
            #pragma unroll
            for (int hh = 0; hh < 2; ++hh) {
                int m = hh * 32 + lr;
                float4 a = *(const float4*)(h_in + (size_t)(bm * TM + m) * HID + kb + kq * 4);
                A_s[(kq * 4 + 0) * AS_STRIDE + m] = a.x;
                A_s[(kq * 4 + 1) * AS_STRIDE + m] = a.y;
                A_s[(kq * 4 + 2) * AS_STRIDE + m] = a.z;
                A_s[(kq * 4 + 3) * AS_STRIDE + m] = a.w;
            }
        }
        __syncthreads();

        const float* Ab = (kc < 2) ? (emb_s + kc * TK * AS_STRIDE) : A_s;
        #pragma unroll 8
        for (int kk = 0; kk < TK; ++kk) {
            float4 av = *(const float4*)(Ab + kk * AS_STRIDE + ty * 4);
            float4 b0 = *(const float4*)(W_s + kk * WS_STRIDE + tx * 8);
            float4 b1 = *(const float4*)(W_s + kk * WS_STRIDE + tx * 8 + 4);
            float a[4] = {av.x, av.y, av.z, av.w};
            float b[8] = {b0.x, b0.y, b0.z, b0.w, b1.x, b1.y, b1.z, b1.w};
            #pragma unroll
            for (int mi = 0; mi < 4; ++mi)
                #pragma unroll
                for (int ni = 0; ni < 8; ++ni)
                    acc[mi][ni] = fmaf(a[mi], b[ni], acc[mi][ni]);
        }
        __syncthreads();
    }

    // ---- exchange gates through smem so each thread owns i,f,g,o of a cell ----
    #pragma unroll
    for (int mi = 0; mi < 4; ++mi)
        #pragma unroll
        for (int ni = 0; ni < 8; ++ni) {
            int n = tx * 8 + ni;
            int g = n >> 5, jj = n & 31, m = ty * 4 + mi;
            gbuf[g * GB_GSTRIDE + m * GB_MSTRIDE + jj] = acc[mi][ni];
        }
    __syncthreads();

    // ---- LSTM cell update (2048 cells / 256 threads = 8 each, coalesced) ----
    #pragma unroll
    for (int u = 0; u < 8; ++u) {
        int idx = tid + 256 * u;
        int m = idx >> 5, jj = idx & 31;
        size_t gi = (size_t)(bm * TM + m) * HID + bn * TN + jj;
        float xi = sigf (gbuf[0 * GB_GSTRIDE + m * GB_MSTRIDE + jj]);
        float xf = sigf (gbuf[1 * GB_GSTRIDE + m * GB_MSTRIDE + jj]);
        float xg = tanhf(gbuf[2 * GB_GSTRIDE + m * GB_MSTRIDE + jj]);
        float xo = sigf (gbuf[3 * GB_GSTRIDE + m * GB_MSTRIDE + jj]);
        float cold = (s == 0) ? 0.0f : g_c[gi];
        float cnew = fmaf(xf, cold, xi * xg);
        g_c[gi]   = cnew;
        h_out[gi] = xo * tanhf(cnew);
    }
}

// Output projection: out[s] = h @ W_out^T + b_out   ([4096, 5])
extern "C" __global__ void __launch_bounds__(256)
out_proj_kernel(const float* __restrict__ W_out, const float* __restrict__ b_out,
                float* __restrict__ out, int s)
{
    __shared__ float ws[5 * HID];
    const float* h = g_h[s & 1];
    for (int i = threadIdx.x; i < 5 * HID; i += 256) ws[i] = W_out[i];
    __syncthreads();

    int w = threadIdx.x >> 5, lane = threadIdx.x & 31;
    int row = blockIdx.x * 8 + w;
    const float* hr = h + (size_t)row * HID;

    float a0 = 0.f, a1 = 0.f, a2 = 0.f, a3 = 0.f, a4 = 0.f;
    #pragma unroll 8
    for (int it = 0; it < HID / 32; ++it) {
        int k = lane + it * 32;
        float a = hr[k];
        a0 = fmaf(a, ws[0 * HID + k], a0);
        a1 = fmaf(a, ws[1 * HID + k], a1);
        a2 = fmaf(a, ws[2 * HID + k], a2);
        a3 = fmaf(a, ws[3 * HID + k], a3);
        a4 = fmaf(a, ws[4 * HID + k], a4);
    }
    #pragma unroll
    for (int off = 16; off; off >>= 1) {
        a0 += __shfl_xor_sync(0xffffffff, a0, off);
        a1 += __shfl_xor_sync(0xffffffff, a1, off);
        a2 += __shfl_xor_sync(0xffffffff, a2, off);
        a3 += __shfl_xor_sync(0xffffffff, a3, off);
        a4 += __shfl_xor_sync(0xffffffff, a4, off);
    }
    if (lane == 0) {
        float* o = out + (size_t)s * BATCH * 5 + (size_t)row * 5;
        o[0] = a0 + b_out[0];
        o[1] = a1 + b_out[1];
        o[2] = a2 + b_out[2];
        o[3] = a3 + b_out[3];
        o[4] = a4 + b_out[4];
    }
}

extern "C" void kernel_launch(void* const* d_in, const int* in_sizes, int n_in,
                              void* d_out, int out_size)
{
    const float* observed = (const float*)d_in[0];
    const float* W_emb    = (const float*)d_in[1];
    const float* b_emb    = (const float*)d_in[2];
    const float* W_ih     = (const float*)d_in[3];
    const float* b_ih     = (const float*)d_in[4];
    const float* W_hh     = (const float*)d_in[5];
    const float* b_hh     = (const float*)d_in[6];
    const float* W_out    = (const float*)d_in[7];
    const float* b_out    = (const float*)d_in[8];
    float* out = (float*)d_out;

    // smem: emb(64*68) + max(tiles(32*68+32*132)=6400, gates(4*64*33)=8448) floats
    const size_t smem = (size_t)(EMBD * AS_STRIDE + 4 * 64 * GB_MSTRIDE) * sizeof(float); // 51200 B
    cudaFuncSetAttribute(lstm_step_kernel, cudaFuncAttributeMaxDynamicSharedMemorySize, (int)smem);

    dim3 grid(HID / TN, BATCH / TM);  // (32, 64) = 2048 blocks

    for (int s = 0; s < NSTEPS; ++s) {
        lstm_step_kernel<<<grid, 256, smem>>>(observed, W_emb, b_emb,
                                              W_ih, b_ih, W_hh, b_hh, out, s);
        out_proj_kernel<<<BATCH / 8, 256>>>(W_out, b_out, out, s);
    }
}

// round 9
// speedup vs baseline: 6.6389x; 6.6389x over previous
#include <cuda_runtime.h>
#include <cuda_bf16.h>
#include <math.h>
#include <stdint.h>

// Problem constants
#define BATCH   4096
#define HID     1024
#define EMBD    64
#define KDIM    1088          // EMBD + HID
#define NOBS    8
#define NSTEPS  19
#define GROWS   4096          // 4*HID gate rows

// GEMM tiling
#define TM      128           // batch rows per CTA
#define TN      128           // permuted gate cols per CTA = 32 hidden units x 4 gates
#define TKC     64            // K chunk (64 bf16 = 128B rows -> SW128 swizzle)

// smem layout (byte offsets from 1024-aligned base)
#define SA0     0
#define SA1     16384
#define SB0     32768
#define SB1     49152
#define GB_STRIDE 132         // floats per gbuf row
#define SBIAS   67584         // gbuf = 128*132*4 = 67584 (overlays A/B buffers)
#define SMEM_BYTES (67584 + 512 + 1024)   // + bias + alignment pad

// ---------------- device state (allocation-free scratch) ----------------
__device__ __nv_bfloat16 g_Xhi[BATCH * KDIM];     // [emb(64) | h(1024)] hi
__device__ __nv_bfloat16 g_Xlo[BATCH * KDIM];     // lo residual
__device__ __nv_bfloat16 g_Wphi[GROWS * KDIM];    // permuted [W_ih|W_hh] hi
__device__ __nv_bfloat16 g_Wplo[GROWS * KDIM];    // lo residual
__device__ float         g_bp[GROWS];             // permuted b_ih+b_hh
__device__ float         g_c[BATCH * HID];        // cell state (fp32)

// ---------------- helpers ----------------
__device__ __forceinline__ uint32_t smem_u32(const void* p) {
    uint32_t a;
    asm("{ .reg .u64 t; cvta.to.shared.u64 t, %1; cvt.u32.u64 %0, t; }" : "=r"(a) : "l"(p));
    return a;
}
__device__ __forceinline__ void cp16(uint32_t dst, const void* src) {
    asm volatile("cp.async.cg.shared.global [%0], [%1], 16;" :: "r"(dst), "l"(src));
}
#define CP_COMMIT() asm volatile("cp.async.commit_group;" ::: "memory")
__device__ __forceinline__ uint32_t swz(uint32_t off) { return off ^ ((off >> 3) & 0x70); }

__device__ __forceinline__ void ldmat4(uint32_t* r, uint32_t addr) {
    asm volatile("ldmatrix.sync.aligned.m8n8.x4.shared.b16 {%0,%1,%2,%3}, [%4];"
        : "=r"(r[0]), "=r"(r[1]), "=r"(r[2]), "=r"(r[3]) : "r"(addr));
}
__device__ __forceinline__ void mma16816(float* c, const uint32_t* a, uint32_t b0, uint32_t b1) {
    asm volatile("mma.sync.aligned.m16n8k16.row.col.f32.bf16.bf16.f32 "
        "{%0,%1,%2,%3}, {%4,%5,%6,%7}, {%8,%9}, {%0,%1,%2,%3};"
        : "+f"(c[0]), "+f"(c[1]), "+f"(c[2]), "+f"(c[3])
        : "r"(a[0]), "r"(a[1]), "r"(a[2]), "r"(a[3]), "r"(b0), "r"(b1));
}

__device__ __forceinline__ float sigf(float x) {
    return __fdividef(1.0f, 1.0f + __expf(-x));
}
__device__ __forceinline__ float tanh_f(float x) {
    return fmaf(2.0f, sigf(2.0f * x), -1.0f);
}

// Load one K-chunk: A[128 x 64] + B[128 x 64] bf16, SW128-swizzled, via cp.async
__device__ __forceinline__ void load_chunk(uint32_t Aoff, uint32_t Boff,
                                           const __nv_bfloat16* __restrict__ Asrc,
                                           const __nv_bfloat16* __restrict__ Bsrc,
                                           int bm, int bn, int kbase, int tid)
{
    #pragma unroll
    for (int u = 0; u < 4; ++u) {                 // A: 1024 x 16B
        int idx = tid + 256 * u;
        int r = idx >> 3, q = idx & 7;
        const void* src = Asrc + (size_t)(bm * TM + r) * KDIM + kbase + q * 8;
        cp16(Aoff + swz((uint32_t)(r * 128 + q * 16)), src);
    }
    #pragma unroll
    for (int u = 0; u < 4; ++u) {                 // B: 1024 x 16B
        int idx = tid + 256 * u;
        int r = idx >> 3, q = idx & 7;
        const void* src = Bsrc + (size_t)(bn * TN + r) * KDIM + kbase + q * 8;
        cp16(Boff + swz((uint32_t)(r * 128 + q * 16)), src);
    }
    CP_COMMIT();
}

// ---------------- one-time prep: permute+split W, combine biases ----------------
extern "C" __global__ void __launch_bounds__(256)
prep_kernel(const float* __restrict__ W_ih, const float* __restrict__ b_ih,
            const float* __restrict__ W_hh, const float* __restrict__ b_hh)
{
    int idx = blockIdx.x * 256 + threadIdx.x;       // 0 .. GROWS*KDIM
    int ro = idx / KDIM, k = idx - ro * KDIM;
    int j = ro >> 2, q = ro & 3;                    // ro = j*4 + gate
    int orig = q * HID + j;
    float v = (k < EMBD) ? W_ih[(size_t)orig * EMBD + k]
                         : W_hh[(size_t)orig * HID + (k - EMBD)];
    __nv_bfloat16 hi = __float2bfloat16(v);
    g_Wphi[idx] = hi;
    g_Wplo[idx] = __float2bfloat16(v - __bfloat162float(hi));
    if (k == 0) g_bp[ro] = b_ih[orig] + b_hh[orig];
}

// ---------------- per-step embedding -> X cols 0..63 ----------------
extern "C" __global__ void __launch_bounds__(256)
emb_kernel(const float* __restrict__ observed, const float* __restrict__ W_emb,
           const float* __restrict__ b_emb, const float* __restrict__ out, int s)
{
    int idx = blockIdx.x * 256 + threadIdx.x;       // 0 .. BATCH*EMBD
    int row = idx >> 6, e = idx & 63;
    float d0, d1;
    if (s < NOBS) {
        const float* o1 = observed + (size_t)(s + 1) * BATCH * 2 + (size_t)row * 2;
        const float* o0 = observed + (size_t)s       * BATCH * 2 + (size_t)row * 2;
        d0 = o1[0] - o0[0];
        d1 = o1[1] - o0[1];
    } else {
        const float* pv = out + (size_t)(s - 1) * BATCH * 5 + (size_t)row * 5;
        d0 = pv[0];
        d1 = pv[1];
    }
    float v = fmaf(W_emb[e * 2], d0, fmaf(W_emb[e * 2 + 1], d1, b_emb[e]));
    v = fmaxf(v, 0.0f);
    __nv_bfloat16 hi = __float2bfloat16(v);
    g_Xhi[(size_t)row * KDIM + e] = hi;
    g_Xlo[(size_t)row * KDIM + e] = __float2bfloat16(v - __bfloat162float(hi));
}

// ---------------- fused gates GEMM (mma.sync bf16) + LSTM cell update ----------------
extern "C" __global__ void __launch_bounds__(256, 2)
gates_kernel(int s)
{
    extern __shared__ char smraw[];
    const uint32_t sm0  = smem_u32(smraw);
    const uint32_t base = (sm0 + 1023) & ~1023u;
    const uint32_t pad  = base - sm0;
    const uint32_t Aoff[2] = {base + SA0, base + SA1};
    const uint32_t Boff[2] = {base + SB0, base + SB1};

    const int tid  = threadIdx.x;
    const int wid  = tid >> 5;
    const int lane = tid & 31;
    const int wm   = wid >> 2;      // 0..1 : warp M position (64 rows each)
    const int wn   = wid & 3;       // 0..3 : warp N position (32 cols each)
    const int bn   = blockIdx.x;    // 0..31 (permuted gate-col tile)
    const int bm   = blockIdx.y;    // 0..31 (batch tile)

    // kick off first chunk ASAP (pass 0, chunk 0)
    load_chunk(Aoff[0], Boff[0], g_Xhi, g_Wphi, bm, bn, 0, tid);

    float* bias_s = (float*)(smraw + pad + SBIAS);
    if (tid < TN) bias_s[tid] = g_bp[bn * TN + tid];

    const __nv_bfloat16* Apass[3] = {g_Xhi, g_Xhi, g_Xlo};
    const __nv_bfloat16* Bpass[3] = {g_Wphi, g_Wplo, g_Wphi};

    float acc[4][4][4];
    #pragma unroll
    for (int mt = 0; mt < 4; ++mt)
        #pragma unroll
        for (int nt = 0; nt < 4; ++nt)
            #pragma unroll
            for (int v = 0; v < 4; ++v) acc[mt][nt][v] = 0.0f;

    const int niter = (s == 0) ? 3 : 51;   // step 0: h==0, only emb K-chunk per pass
    const int lrow  = lane & 15;
    const int lhalf = (lane >> 4) * 16;

    for (int it = 0; it < niter; ++it) {
        const int b = it & 1, nb = b ^ 1;
        if (it + 1 < niter) {
            const int nit = it + 1;
            const int p = (s == 0) ? nit : (nit / 17);
            const int c = (s == 0) ? 0   : (nit % 17);
            load_chunk(Aoff[nb], Boff[nb], Apass[p], Bpass[p], bm, bn, c * TKC, tid);
            asm volatile("cp.async.wait_group 1;" ::: "memory");
        } else {
            asm volatile("cp.async.wait_group 0;" ::: "memory");
        }
        __syncthreads();

        const uint32_t ab = Aoff[b], bb = Boff[b];
        #pragma unroll
        for (int kk = 0; kk < 4; ++kk) {
            uint32_t afr[4][4], bfr[2][4];
            #pragma unroll
            for (int mt = 0; mt < 4; ++mt) {
                int row = wm * 64 + mt * 16 + lrow;
                ldmat4(afr[mt], ab + swz((uint32_t)(row * 128 + kk * 32 + lhalf)));
            }
            #pragma unroll
            for (int nt2 = 0; nt2 < 2; ++nt2) {
                int row = wn * 32 + nt2 * 16 + lrow;
                ldmat4(bfr[nt2], bb + swz((uint32_t)(row * 128 + kk * 32 + lhalf)));
            }
            #pragma unroll
            for (int mt = 0; mt < 4; ++mt)
                #pragma unroll
                for (int nt = 0; nt < 4; ++nt) {
                    const uint32_t* bf = bfr[nt >> 1];
                    uint32_t b0 = (nt & 1) ? bf[1] : bf[0];
                    uint32_t b1 = (nt & 1) ? bf[3] : bf[2];
                    mma16816(acc[mt][nt], afr[mt], b0, b1);
                }
        }
        __syncthreads();
    }

    // ------- dump accumulators to smem (gbuf overlays A/B buffers) -------
    float* gbuf = (float*)(smraw + pad);
    #pragma unroll
    for (int mt = 0; mt < 4; ++mt)
        #pragma unroll
        for (int nt = 0; nt < 4; ++nt) {
            int r0 = wm * 64 + mt * 16 + (lane >> 2);
            int c  = wn * 32 + nt * 8 + (lane & 3) * 2;
            *(float2*)&gbuf[r0 * GB_STRIDE + c]       = make_float2(acc[mt][nt][0], acc[mt][nt][1]);
            *(float2*)&gbuf[(r0 + 8) * GB_STRIDE + c] = make_float2(acc[mt][nt][2], acc[mt][nt][3]);
        }
    __syncthreads();

    // ------- fused LSTM cell update: 128 rows x 32 hidden units per CTA -------
    #pragma unroll
    for (int u = 0; u < 16; ++u) {
        int idx = tid + 256 * u;       // 0..4095
        int m = idx >> 5, j = idx & 31;
        int row = bm * TM + m;
        int jglob = bn * 32 + j;
        const float* gp = &gbuf[m * GB_STRIDE + j * 4];
        float gi = gp[0] + bias_s[j * 4 + 0];
        float gf = gp[1] + bias_s[j * 4 + 1];
        float gg = gp[2] + bias_s[j * 4 + 2];
        float go = gp[3] + bias_s[j * 4 + 3];
        float xi = sigf(gi), xf = sigf(gf);
        float xg = tanh_f(gg), xo = sigf(go);
        size_t ci = (size_t)row * HID + jglob;
        float cold = (s > 0) ? g_c[ci] : 0.0f;
        float cn = fmaf(xf, cold, xi * xg);
        g_c[ci] = cn;
        float hn = xo * tanh_f(cn);
        __nv_bfloat16 hb = __float2bfloat16(hn);
        g_Xhi[(size_t)row * KDIM + EMBD + jglob] = hb;
        g_Xlo[(size_t)row * KDIM + EMBD + jglob] =
            __float2bfloat16(hn - __bfloat162float(hb));
    }
}

// ---------------- output projection: out[s] = h @ W_out^T + b_out ----------------
extern "C" __global__ void __launch_bounds__(256)
out_proj_kernel(const float* __restrict__ W_out, const float* __restrict__ b_out,
                float* __restrict__ out, int s)
{
    __shared__ float ws[5 * HID];
    for (int i = threadIdx.x; i < 5 * HID; i += 256) ws[i] = W_out[i];
    __syncthreads();

    int w = threadIdx.x >> 5, lane = threadIdx.x & 31;
    int row = blockIdx.x * 8 + w;
    const __nv_bfloat16* xh = g_Xhi + (size_t)row * KDIM + EMBD;
    const __nv_bfloat16* xl = g_Xlo + (size_t)row * KDIM + EMBD;

    float a0 = 0.f, a1 = 0.f, a2 = 0.f, a3 = 0.f, a4 = 0.f;
    #pragma unroll
    for (int it = 0; it < 4; ++it) {
        int k0 = it * 256 + lane * 8;
        union { uint4 v; __nv_bfloat16 bb[8]; } uh, ul;
        uh.v = *(const uint4*)(xh + k0);
        ul.v = *(const uint4*)(xl + k0);
        #pragma unroll
        for (int t = 0; t < 8; ++t) {
            float a = __bfloat162float(uh.bb[t]) + __bfloat162float(ul.bb[t]);
            int k = k0 + t;
            a0 = fmaf(a, ws[0 * HID + k], a0);
            a1 = fmaf(a, ws[1 * HID + k], a1);
            a2 = fmaf(a, ws[2 * HID + k], a2);
            a3 = fmaf(a, ws[3 * HID + k], a3);
            a4 = fmaf(a, ws[4 * HID + k], a4);
        }
    }
    #pragma unroll
    for (int off = 16; off; off >>= 1) {
        a0 += __shfl_xor_sync(0xffffffff, a0, off);
        a1 += __shfl_xor_sync(0xffffffff, a1, off);
        a2 += __shfl_xor_sync(0xffffffff, a2, off);
        a3 += __shfl_xor_sync(0xffffffff, a3, off);
        a4 += __shfl_xor_sync(0xffffffff, a4, off);
    }
    if (lane == 0) {
        float* o = out + (size_t)s * BATCH * 5 + (size_t)row * 5;
        o[0] = a0 + b_out[0];
        o[1] = a1 + b_out[1];
        o[2] = a2 + b_out[2];
        o[3] = a3 + b_out[3];
        o[4] = a4 + b_out[4];
    }
}

extern "C" void kernel_launch(void* const* d_in, const int* in_sizes, int n_in,
                              void* d_out, int out_size)
{
    const float* observed = (const float*)d_in[0];
    const float* W_emb    = (const float*)d_in[1];
    const float* b_emb    = (const float*)d_in[2];
    const float* W_ih     = (const float*)d_in[3];
    const float* b_ih     = (const float*)d_in[4];
    const float* W_hh     = (const float*)d_in[5];
    const float* b_hh     = (const float*)d_in[6];
    const float* W_out    = (const float*)d_in[7];
    const float* b_out    = (const float*)d_in[8];
    float* out = (float*)d_out;

    cudaFuncSetAttribute(gates_kernel, cudaFuncAttributeMaxDynamicSharedMemorySize, SMEM_BYTES);

    prep_kernel<<<(GROWS * KDIM) / 256, 256>>>(W_ih, b_ih, W_hh, b_hh);

    dim3 grid(GROWS / TN, BATCH / TM);   // (32, 32)
    for (int s = 0; s < NSTEPS; ++s) {
        emb_kernel<<<(BATCH * EMBD) / 256, 256>>>(observed, W_emb, b_emb, out, s);
        gates_kernel<<<grid, 256, SMEM_BYTES>>>(s);
        out_proj_kernel<<<BATCH / 8, 256>>>(W_out, b_out, out, s);
    }
}